// round 8
// baseline (speedup 1.0000x reference)
#include <cuda_runtime.h>
#include <cstdint>

#define S0_N 663552
#define S1_N 73728
#define S2_N 8192
#define FEAT 128
#define CONT 256
#define FAN  8

// ---------------- scratch (static device globals; no allocation) ------------
__device__ float g_h0[(size_t)S0_N * FEAT];   // ~324 MB
__device__ float g_h1[(size_t)S1_N * FEAT];   // ~36 MB
__device__ unsigned char g_flag[S0_N];
__device__ int g_list[S0_N];
__device__ int g_count;

// ---------------- helpers ---------------------------------------------------
__device__ __forceinline__ float leakyf(float x) { return x > 0.f ? x : 0.1f * x; }

__device__ __forceinline__ unsigned long long packf2(float a, float b) {
    unsigned long long r;
    asm("mov.b64 %0, {%1, %2};" : "=l"(r)
        : "r"(__float_as_uint(a)), "r"(__float_as_uint(b)));
    return r;
}
__device__ __forceinline__ void unpackf2(unsigned long long v, float& a, float& b) {
    unsigned int u0, u1;
    asm("mov.b64 {%0, %1}, %2;" : "=r"(u0), "=r"(u1) : "l"(v));
    a = __uint_as_float(u0); b = __uint_as_float(u1);
}
__device__ __forceinline__ unsigned long long fma2(unsigned long long a,
                                                   unsigned long long b,
                                                   unsigned long long c) {
    unsigned long long d;
    asm("fma.rn.f32x2 %0, %1, %2, %3;" : "=l"(d) : "l"(a), "l"(b), "l"(c));
    return d;
}

// ---------------- tiny setup kernels ----------------------------------------
__global__ void k_reset() {
    int t = blockIdx.x * blockDim.x + threadIdx.x;
    if (t < S0_N / 16) ((int4*)g_flag)[t] = make_int4(0, 0, 0, 0);
    if (t == 0) g_count = 0;
}

__global__ void k_mark(const int* __restrict__ src0) {
    int t = blockIdx.x * blockDim.x + threadIdx.x;   // grid covers 9*S1 exactly
    g_flag[src0[t]] = 1;
    if (t < S1_N) g_flag[t] = 1;
}

__global__ void k_compact() {
    int t = blockIdx.x * blockDim.x + threadIdx.x;   // grid covers S0 exactly
    int f = (g_flag[t] != 0);
    unsigned m = __ballot_sync(0xffffffffu, f);
    int lane = threadIdx.x & 31;
    int base = 0;
    if (lane == 0) base = atomicAdd(&g_count, __popc(m));
    base = __shfl_sync(0xffffffffu, base, 0);
    if (f) g_list[base + __popc(m & ((1u << lane) - 1u))] = t;
}

// ---------------- h0 = node_emb[parent+1] + leaky(content @ Wp^T + bp) ------
// tile: 128 needed-rows x 128 feats, 256 threads (16x16), f32x2 accumulators
__global__ void __launch_bounds__(256, 2) k_h0(
    const float* __restrict__ content, const float* __restrict__ Wp,
    const float* __restrict__ bp, const float* __restrict__ node_emb,
    const int* __restrict__ parent)
{
    __shared__ float cs[128 * 36];   // content tile, row-major padded
    __shared__ float ws[32 * 132];   // Wp tile transposed [k][f], padded
    __shared__ int rid_s[128];
    __shared__ int par_s[128];

    int cnt = g_count;
    int b0r = blockIdx.x * 128;
    if (b0r >= cnt) return;

    int t = threadIdx.x;
    if (t < 128) {
        int g = b0r + t;
        int rid = g_list[(g < cnt) ? g : (cnt - 1)];
        rid_s[t] = rid;
        par_s[t] = parent[rid] + 1;
    }
    __syncthreads();

    const int ty = t >> 4, tx = t & 15;
    const int lrow = t >> 1, lhalf = t & 1;
    const size_t crow = (size_t)rid_s[lrow] * CONT;

    unsigned long long acc[8][4];
#pragma unroll
    for (int r = 0; r < 8; r++)
#pragma unroll
        for (int j = 0; j < 4; j++) acc[r][j] = 0ull;

    for (int kc = 0; kc < CONT; kc += 32) {
        // content tile 128x32 (each thread: one half-row of 16 floats)
#pragma unroll
        for (int j4 = 0; j4 < 4; j4++) {
            float4 v = *(const float4*)(content + crow + kc + lhalf * 16 + j4 * 4);
            *(float4*)(cs + lrow * 36 + lhalf * 16 + j4 * 4) = v;
        }
        // Wp tile, transposed into ws[k][f]
#pragma unroll
        for (int j4 = 0; j4 < 4; j4++) {
            float4 v = *(const float4*)(Wp + (size_t)lrow * CONT + kc + lhalf * 16 + j4 * 4);
            int kk = lhalf * 16 + j4 * 4;
            ws[(kk + 0) * 132 + lrow] = v.x;
            ws[(kk + 1) * 132 + lrow] = v.y;
            ws[(kk + 2) * 132 + lrow] = v.z;
            ws[(kk + 3) * 132 + lrow] = v.w;
        }
        __syncthreads();

#pragma unroll
        for (int k = 0; k < 32; k++) {
            const unsigned long long* wp64 =
                (const unsigned long long*)(ws + k * 132 + tx * 8);
            unsigned long long b0v = wp64[0], b1v = wp64[1], b2v = wp64[2], b3v = wp64[3];
#pragma unroll
            for (int r = 0; r < 8; r++) {
                float a = cs[(ty * 8 + r) * 36 + k];
                unsigned long long a2 = packf2(a, a);
                acc[r][0] = fma2(a2, b0v, acc[r][0]);
                acc[r][1] = fma2(a2, b1v, acc[r][1]);
                acc[r][2] = fma2(a2, b2v, acc[r][2]);
                acc[r][3] = fma2(a2, b3v, acc[r][3]);
            }
        }
        __syncthreads();
    }

    float bpv[8];
#pragma unroll
    for (int j = 0; j < 8; j++) bpv[j] = bp[tx * 8 + j];

#pragma unroll
    for (int r = 0; r < 8; r++) {
        int lr = ty * 8 + r;
        if (b0r + lr >= cnt) continue;
        int rid = rid_s[lr];
        const float* ne = node_emb + (size_t)par_s[lr] * FEAT + tx * 8;
        float* dst = g_h0 + (size_t)rid * FEAT + tx * 8;
        float o[8];
#pragma unroll
        for (int j = 0; j < 4; j++) {
            float x0, x1;
            unpackf2(acc[r][j], x0, x1);
            o[2 * j]     = leakyf(x0 + bpv[2 * j]);
            o[2 * j + 1] = leakyf(x1 + bpv[2 * j + 1]);
        }
        float4 n0 = *(const float4*)(ne);
        float4 n1 = *(const float4*)(ne + 4);
        *(float4*)(dst)     = make_float4(o[0] + n0.x, o[1] + n0.y, o[2] + n0.z, o[3] + n0.w);
        *(float4*)(dst + 4) = make_float4(o[4] + n1.x, o[5] + n1.y, o[6] + n1.z, o[7] + n1.w);
    }
}

// ---------------- SAGE conv layer -------------------------------------------
// block: 64 dst rows x 128 out-feats; gather 9 neighbors, build X=[h_dst,h_agg]
// in smem, then dual GEMM (W over 256 cols + Wagg over h_agg) with f32x2.
#define CONV_SMEM_FLOATS (64 * 260 + 3 * 16 * 132)
#define CONV_SMEM_BYTES (CONV_SMEM_FLOATS * 4)

template <int LAST>
__global__ void __launch_bounds__(256, 2) k_conv(
    const float* __restrict__ hsrc, const float* __restrict__ hdst,
    const int* __restrict__ srcArr, int n_dst,
    const float* __restrict__ W, const float* __restrict__ bb,
    const float* __restrict__ Wagg, const float* __restrict__ bagg,
    float* __restrict__ out)
{
    extern __shared__ float sm[];
    float* Xs = sm;                   // [64][260]  cols 0..127 h_dst, 128..255 h_agg
    float* Wa = sm + 64 * 260;        // [16][132]  W[:, kc+k]
    float* Wb = Wa + 16 * 132;        // [16][132]  W[:, 128+kc+k]
    float* Wg = Wb + 16 * 132;        // [16][132]  Wagg[:, kc+k]

    const int t = threadIdx.x;

    // ---- gather phase: 4 threads per row, 32 feats each ----
    {
        int row = t >> 2, q = t & 3, f0 = q * 32;
        size_t i = (size_t)blockIdx.x * 64 + row;
        const float* pd = hdst + i * FEAT + f0;
        const float* ps = hsrc + i * FEAT + f0;
        float4 hd[8], s[8];
#pragma unroll
        for (int j = 0; j < 8; j++) {
            hd[j] = *(const float4*)(pd + 4 * j);
            s[j]  = *(const float4*)(ps + 4 * j);   // self edge: h_src[i]
        }
        int eb = n_dst + (int)i * FAN;
#pragma unroll
        for (int e = 0; e < FAN; e++) {
            const float* pe = hsrc + (size_t)srcArr[eb + e] * FEAT + f0;
#pragma unroll
            for (int j = 0; j < 8; j++) {
                float4 u = *(const float4*)(pe + 4 * j);
                s[j].x += u.x; s[j].y += u.y; s[j].z += u.z; s[j].w += u.w;
            }
        }
        float* xr = Xs + row * 260;
#pragma unroll
        for (int j = 0; j < 8; j++) {
            *(float4*)(xr + f0 + 4 * j) = hd[j];
            float4 ag;
            ag.x = (s[j].x - hd[j].x) * 0.125f;
            ag.y = (s[j].y - hd[j].y) * 0.125f;
            ag.z = (s[j].z - hd[j].z) * 0.125f;
            ag.w = (s[j].w - hd[j].w) * 0.125f;
            *(float4*)(xr + 128 + f0 + 4 * j) = ag;
        }
    }
    __syncthreads();

    const int ty = t >> 4, tx = t & 15;
    const int fw = t >> 1, hf = t & 1;

    unsigned long long aN[4][4], aA[4][4];
#pragma unroll
    for (int r = 0; r < 4; r++)
#pragma unroll
        for (int j = 0; j < 4; j++) { aN[r][j] = 0ull; aA[r][j] = 0ull; }

    for (int kc = 0; kc < FEAT; kc += 16) {
#pragma unroll
        for (int j4 = 0; j4 < 2; j4++) {
            int kk = hf * 8 + j4 * 4;
            float4 v  = *(const float4*)(W    + (size_t)fw * 256 + kc + kk);
            float4 v2 = *(const float4*)(W    + (size_t)fw * 256 + 128 + kc + kk);
            float4 v3 = *(const float4*)(Wagg + (size_t)fw * 128 + kc + kk);
            Wa[(kk + 0) * 132 + fw] = v.x;  Wa[(kk + 1) * 132 + fw] = v.y;
            Wa[(kk + 2) * 132 + fw] = v.z;  Wa[(kk + 3) * 132 + fw] = v.w;
            Wb[(kk + 0) * 132 + fw] = v2.x; Wb[(kk + 1) * 132 + fw] = v2.y;
            Wb[(kk + 2) * 132 + fw] = v2.z; Wb[(kk + 3) * 132 + fw] = v2.w;
            Wg[(kk + 0) * 132 + fw] = v3.x; Wg[(kk + 1) * 132 + fw] = v3.y;
            Wg[(kk + 2) * 132 + fw] = v3.z; Wg[(kk + 3) * 132 + fw] = v3.w;
        }
        __syncthreads();

#pragma unroll
        for (int k = 0; k < 16; k++) {
            const unsigned long long* pa = (const unsigned long long*)(Wa + k * 132 + tx * 8);
            const unsigned long long* pb = (const unsigned long long*)(Wb + k * 132 + tx * 8);
            const unsigned long long* pg = (const unsigned long long*)(Wg + k * 132 + tx * 8);
            unsigned long long bn[4]  = { pa[0], pa[1], pa[2], pa[3] };
            unsigned long long bn2[4] = { pb[0], pb[1], pb[2], pb[3] };
            unsigned long long bg[4]  = { pg[0], pg[1], pg[2], pg[3] };
#pragma unroll
            for (int ri = 0; ri < 4; ri++) {
                const float* xr = Xs + (ty * 4 + ri) * 260;
                float a1 = xr[kc + k];
                float a2 = xr[128 + kc + k];
                unsigned long long p1 = packf2(a1, a1);
                unsigned long long p2 = packf2(a2, a2);
#pragma unroll
                for (int j = 0; j < 4; j++) {
                    aN[ri][j] = fma2(p1, bn[j],  aN[ri][j]);
                    aN[ri][j] = fma2(p2, bn2[j], aN[ri][j]);
                    aA[ri][j] = fma2(p2, bg[j],  aA[ri][j]);
                }
            }
        }
        __syncthreads();
    }

    // ---- epilogue ----
    float bv[8], bgv[8];
#pragma unroll
    for (int j = 0; j < 8; j++) { bv[j] = bb[tx * 8 + j]; bgv[j] = bagg[tx * 8 + j]; }

#pragma unroll
    for (int ri = 0; ri < 4; ri++) {
        size_t irow = (size_t)blockIdx.x * 64 + ty * 4 + ri;
        float h[8];
#pragma unroll
        for (int j = 0; j < 4; j++) {
            float n0, n1, a0, a1;
            unpackf2(aN[ri][j], n0, n1);
            unpackf2(aA[ri][j], a0, a1);
            float hn0 = n0 + bv[2 * j],  hn1 = n1 + bv[2 * j + 1];
            float ha0 = a0 + bgv[2 * j], ha1 = a1 + bgv[2 * j + 1];
            if (!LAST) { hn0 = leakyf(hn0); hn1 = leakyf(hn1);
                         ha0 = leakyf(ha0); ha1 = leakyf(ha1); }
            h[2 * j] = hn0 + ha0; h[2 * j + 1] = hn1 + ha1;
        }
        if (!LAST) {
            float ss = 0.f;
#pragma unroll
            for (int j = 0; j < 8; j++) ss += h[j] * h[j];
            ss += __shfl_xor_sync(0xffffffffu, ss, 1);
            ss += __shfl_xor_sync(0xffffffffu, ss, 2);
            ss += __shfl_xor_sync(0xffffffffu, ss, 4);
            ss += __shfl_xor_sync(0xffffffffu, ss, 8);
            float inv = 1.0f / fmaxf(sqrtf(ss), 1e-6f);
#pragma unroll
            for (int j = 0; j < 8; j++) h[j] *= inv;
        }
        float* po = out + irow * FEAT + tx * 8;
        *(float4*)(po)     = make_float4(h[0], h[1], h[2], h[3]);
        *(float4*)(po + 4) = make_float4(h[4], h[5], h[6], h[7]);
    }
}

// ---------------- launch -----------------------------------------------------
extern "C" void kernel_launch(void* const* d_in, const int* in_sizes, int n_in,
                              void* d_out, int out_size)
{
    const float* node_emb = (const float*)d_in[0];
    const float* content0 = (const float*)d_in[1];
    const float* Wp       = (const float*)d_in[2];
    const float* bp       = (const float*)d_in[3];
    const float* W0       = (const float*)d_in[4];
    const float* b0       = (const float*)d_in[5];
    const float* Wagg0    = (const float*)d_in[6];
    const float* bagg0    = (const float*)d_in[7];
    const float* W1       = (const float*)d_in[8];
    const float* b1       = (const float*)d_in[9];
    const float* Wagg1    = (const float*)d_in[10];
    const float* bagg1    = (const float*)d_in[11];
    const int*   parent0  = (const int*)d_in[12];
    const int*   src0     = (const int*)d_in[13];
    const int*   src1     = (const int*)d_in[15];
    float* out = (float*)d_out;

    (void)in_sizes; (void)n_in; (void)out_size;

    // opt-in smem (>48KB); host-side attribute set, safe under capture
    cudaFuncSetAttribute(k_conv<0>, cudaFuncAttributeMaxDynamicSharedMemorySize, CONV_SMEM_BYTES);
    cudaFuncSetAttribute(k_conv<1>, cudaFuncAttributeMaxDynamicSharedMemorySize, CONV_SMEM_BYTES);

    void *p0, *p1;
    cudaGetSymbolAddress(&p0, g_h0);
    cudaGetSymbolAddress(&p1, g_h1);
    float* h0p = (float*)p0;
    float* h1p = (float*)p1;

    k_reset  <<<(S0_N / 16 + 255) / 256, 256>>>();
    k_mark   <<<(9 * S1_N) / 256, 256>>>(src0);
    k_compact<<<S0_N / 256, 256>>>();
    k_h0     <<<S0_N / 128, 256>>>(content0, Wp, bp, node_emb, parent0);
    k_conv<0><<<S1_N / 64, 256, CONV_SMEM_BYTES>>>(h0p, h0p, src0, S1_N,
                                                   W0, b0, Wagg0, bagg0, h1p);
    k_conv<1><<<S2_N / 64, 256, CONV_SMEM_BYTES>>>(h1p, h0p, src1, S2_N,
                                                   W1, b1, Wagg1, bagg1, out);
}

// round 9
// speedup vs baseline: 1.1339x; 1.1339x over previous
#include <cuda_runtime.h>
#include <cstdint>

#define S0_N 663552
#define S1_N 73728
#define S2_N 8192
#define FEAT 128
#define CONT 256
#define FAN  8

typedef unsigned long long u64;

// ---------------- scratch (static device globals; no allocation) ------------
__device__ float g_h0[(size_t)S0_N * FEAT];   // ~324 MB
__device__ float g_h1[(size_t)S1_N * FEAT];   // ~36 MB
__device__ unsigned char g_flag[S0_N];
__device__ int g_list[S0_N];
__device__ int g_count;

// ---------------- helpers ---------------------------------------------------
__device__ __forceinline__ float leakyf(float x) { return x > 0.f ? x : 0.1f * x; }

__device__ __forceinline__ u64 packf2(float a, float b) {
    u64 r;
    asm("mov.b64 %0, {%1, %2};" : "=l"(r)
        : "r"(__float_as_uint(a)), "r"(__float_as_uint(b)));
    return r;
}
__device__ __forceinline__ void unpackf2(u64 v, float& a, float& b) {
    unsigned int u0, u1;
    asm("mov.b64 {%0, %1}, %2;" : "=r"(u0), "=r"(u1) : "l"(v));
    a = __uint_as_float(u0); b = __uint_as_float(u1);
}
__device__ __forceinline__ u64 fma2(u64 a, u64 b, u64 c) {
    u64 d;
    asm("fma.rn.f32x2 %0, %1, %2, %3;" : "=l"(d) : "l"(a), "l"(b), "l"(c));
    return d;
}

// ---------------- tiny setup kernels ----------------------------------------
__global__ void k_reset() {
    int t = blockIdx.x * blockDim.x + threadIdx.x;
    if (t < S0_N / 16) ((int4*)g_flag)[t] = make_int4(0, 0, 0, 0);
    if (t == 0) g_count = 0;
}

__global__ void k_mark(const int* __restrict__ src0) {
    int t = blockIdx.x * blockDim.x + threadIdx.x;   // grid covers 9*S1 exactly
    g_flag[src0[t]] = 1;
    if (t < S1_N) g_flag[t] = 1;
}

__global__ void k_compact() {
    int t = blockIdx.x * blockDim.x + threadIdx.x;   // grid covers S0 exactly
    int f = (g_flag[t] != 0);
    unsigned m = __ballot_sync(0xffffffffu, f);
    int lane = threadIdx.x & 31;
    int base = 0;
    if (lane == 0) base = atomicAdd(&g_count, __popc(m));
    base = __shfl_sync(0xffffffffu, base, 0);
    if (f) g_list[base + __popc(m & ((1u << lane) - 1u))] = t;
}

// ---------------- h0 = node_emb[parent+1] + leaky(content @ Wp^T + bp) ------
// 128 rows x 128 cols per block, 256 threads, 8x8 per thread (f32x2 pairs).
// Weights stored as conflict-free paired u64: ws64[k*68 + j*17 + tx] holds
// (W[k][tx+32j], W[k][tx+32j+16]). Content double-buffered through registers.
__global__ void __launch_bounds__(256, 2) k_h0(
    const float* __restrict__ content, const float* __restrict__ Wp,
    const float* __restrict__ bp, const float* __restrict__ node_emb,
    const int* __restrict__ parent)
{
    __shared__ float cs[128 * 36];     // content tile, row-major, pitch 36
    __shared__ u64 ws64[32 * 68];      // weight tile, paired layout
    __shared__ int rid_s[128];
    __shared__ int par_s[128];

    const int cnt = g_count;
    const int b0r = blockIdx.x * 128;
    if (b0r >= cnt) return;

    const int t = threadIdx.x;
    if (t < 128) {
        int g = b0r + t;
        int rid = g_list[(g < cnt) ? g : (cnt - 1)];
        rid_s[t] = rid;
        par_s[t] = parent[rid] + 1;
    }
    __syncthreads();

    const int ty = t >> 4, tx = t & 15;
    const int fw = t >> 1, hf = t & 1;                    // loader roles
    const int wj = fw >> 5, wh = (fw >> 4) & 1, wtx = fw & 15;
    float* wsf = (float*)ws64;

    const float* crow = content + (size_t)rid_s[fw] * CONT + hf * 16;
    const float* wrow = Wp + (size_t)fw * CONT + hf * 16;

    // prefetch chunk 0 content
    float4 pf[4];
#pragma unroll
    for (int j4 = 0; j4 < 4; j4++) pf[j4] = *(const float4*)(crow + j4 * 4);

    u64 acc[8][4];
#pragma unroll
    for (int r = 0; r < 8; r++)
#pragma unroll
        for (int j = 0; j < 4; j++) acc[r][j] = 0ull;

    for (int c = 0; c < 8; c++) {
        const int kc = c * 32;
        // Wp loads (L2-resident) issued before the barrier: latency hides
        float4 wv[4];
#pragma unroll
        for (int j4 = 0; j4 < 4; j4++) wv[j4] = *(const float4*)(wrow + kc + j4 * 4);

        if (c) __syncthreads();      // previous chunk's compute done

        // content tile store
#pragma unroll
        for (int j4 = 0; j4 < 4; j4++)
            *(float4*)(cs + fw * 36 + hf * 16 + j4 * 4) = pf[j4];
        // weight scatter into paired layout
#pragma unroll
        for (int j4 = 0; j4 < 4; j4++) {
            const float* w4 = (const float*)&wv[j4];
#pragma unroll
            for (int e = 0; e < 4; e++) {
                int k = hf * 16 + j4 * 4 + e;
                wsf[2 * (k * 68 + wj * 17 + wtx) + wh] = w4[e];
            }
        }
        __syncthreads();

        // prefetch next chunk's content while computing this one
        if (c < 7) {
#pragma unroll
            for (int j4 = 0; j4 < 4; j4++)
                pf[j4] = *(const float4*)(crow + kc + 32 + j4 * 4);
        }

#pragma unroll 4
        for (int kk = 0; kk < 32; kk += 2) {
            u64 w0[4], w1[4];
#pragma unroll
            for (int j = 0; j < 4; j++) {
                w0[j] = ws64[kk * 68 + j * 17 + tx];
                w1[j] = ws64[(kk + 1) * 68 + j * 17 + tx];
            }
#pragma unroll
            for (int r = 0; r < 8; r++) {
                float2 ap = *(const float2*)(cs + (ty * 8 + r) * 36 + kk);
                u64 a0 = packf2(ap.x, ap.x);
                u64 a1 = packf2(ap.y, ap.y);
#pragma unroll
                for (int j = 0; j < 4; j++) {
                    acc[r][j] = fma2(a0, w0[j], acc[r][j]);
                    acc[r][j] = fma2(a1, w1[j], acc[r][j]);
                }
            }
        }
    }

    // epilogue: columns for acc[r][j] are (tx+32j, tx+32j+16)
    float bpv[4][2];
#pragma unroll
    for (int j = 0; j < 4; j++) {
        bpv[j][0] = bp[tx + 32 * j];
        bpv[j][1] = bp[tx + 32 * j + 16];
    }

#pragma unroll
    for (int r = 0; r < 8; r++) {
        int lr = ty * 8 + r;
        if (b0r + lr >= cnt) continue;
        const float* ne = node_emb + (size_t)par_s[lr] * FEAT;
        float* dst = g_h0 + (size_t)rid_s[lr] * FEAT;
#pragma unroll
        for (int j = 0; j < 4; j++) {
            float x0, x1;
            unpackf2(acc[r][j], x0, x1);
            int c0 = tx + 32 * j;
            dst[c0]      = leakyf(x0 + bpv[j][0]) + ne[c0];
            dst[c0 + 16] = leakyf(x1 + bpv[j][1]) + ne[c0 + 16];
        }
    }
}

// ---------------- SAGE conv layer -------------------------------------------
// 64 dst rows x 128 cols per block; X=[h_dst,h_agg] in smem; dual GEMM with
// conflict-free paired weights for W (both halves) and Wagg.
#define CONV_SMEM_BYTES (64 * 260 * 4 + 3 * 16 * 68 * 8)

template <int LAST>
__global__ void __launch_bounds__(256, 2) k_conv(
    const float* __restrict__ hsrc, const float* __restrict__ hdst,
    const int* __restrict__ srcArr, int n_dst,
    const float* __restrict__ W, const float* __restrict__ bb,
    const float* __restrict__ Wagg, const float* __restrict__ bagg,
    float* __restrict__ out)
{
    extern __shared__ float sm[];
    float* Xs = sm;                        // [64][260]
    u64* WaP = (u64*)(sm + 64 * 260);      // [16][4][17] pairs, W cols kc..
    u64* WbP = WaP + 16 * 68;              // W cols 128+kc..
    u64* WgP = WbP + 16 * 68;              // Wagg cols kc..

    const int t = threadIdx.x;

    // ---- gather phase: 4 threads per row, 32 feats each ----
    {
        int row = t >> 2, q = t & 3, f0 = q * 32;
        size_t i = (size_t)blockIdx.x * 64 + row;
        const float* pd = hdst + i * FEAT + f0;
        const float* ps = hsrc + i * FEAT + f0;
        float4 hd[8], s[8];
#pragma unroll
        for (int j = 0; j < 8; j++) {
            hd[j] = *(const float4*)(pd + 4 * j);
            s[j]  = *(const float4*)(ps + 4 * j);   // self edge: h_src[i]
        }
        int eb = n_dst + (int)i * FAN;
#pragma unroll
        for (int e = 0; e < FAN; e++) {
            const float* pe = hsrc + (size_t)srcArr[eb + e] * FEAT + f0;
#pragma unroll
            for (int j = 0; j < 8; j++) {
                float4 u = *(const float4*)(pe + 4 * j);
                s[j].x += u.x; s[j].y += u.y; s[j].z += u.z; s[j].w += u.w;
            }
        }
        float* xr = Xs + row * 260;
#pragma unroll
        for (int j = 0; j < 8; j++) {
            *(float4*)(xr + f0 + 4 * j) = hd[j];
            float4 ag;
            ag.x = (s[j].x - hd[j].x) * 0.125f;
            ag.y = (s[j].y - hd[j].y) * 0.125f;
            ag.z = (s[j].z - hd[j].z) * 0.125f;
            ag.w = (s[j].w - hd[j].w) * 0.125f;
            *(float4*)(xr + 128 + f0 + 4 * j) = ag;
        }
    }
    __syncthreads();

    const int ty = t >> 4, tx = t & 15;
    const int fw = t >> 1, hf = t & 1;
    const int wj = fw >> 5, wh = (fw >> 4) & 1, wtx = fw & 15;
    float* waf = (float*)WaP;
    float* wbf = (float*)WbP;
    float* wgf = (float*)WgP;

    u64 aN[4][4], aA[4][4];
#pragma unroll
    for (int r = 0; r < 4; r++)
#pragma unroll
        for (int j = 0; j < 4; j++) { aN[r][j] = 0ull; aA[r][j] = 0ull; }

    for (int kc = 0; kc < FEAT; kc += 16) {
        float4 v[2], v2[2], v3[2];
#pragma unroll
        for (int q = 0; q < 2; q++) {
            v[q]  = *(const float4*)(W    + (size_t)fw * 256 + kc + hf * 8 + q * 4);
            v2[q] = *(const float4*)(W    + (size_t)fw * 256 + 128 + kc + hf * 8 + q * 4);
            v3[q] = *(const float4*)(Wagg + (size_t)fw * 128 + kc + hf * 8 + q * 4);
        }
        if (kc) __syncthreads();
#pragma unroll
        for (int q = 0; q < 2; q++) {
#pragma unroll
            for (int e = 0; e < 4; e++) {
                int k = hf * 8 + q * 4 + e;
                int fi = 2 * (k * 68 + wj * 17 + wtx) + wh;
                waf[fi] = ((const float*)&v[q])[e];
                wbf[fi] = ((const float*)&v2[q])[e];
                wgf[fi] = ((const float*)&v3[q])[e];
            }
        }
        __syncthreads();

#pragma unroll 4
        for (int k = 0; k < 16; k++) {
            u64 wa[4], wb[4], wg[4];
#pragma unroll
            for (int j = 0; j < 4; j++) {
                wa[j] = WaP[k * 68 + j * 17 + tx];
                wb[j] = WbP[k * 68 + j * 17 + tx];
                wg[j] = WgP[k * 68 + j * 17 + tx];
            }
#pragma unroll
            for (int ri = 0; ri < 4; ri++) {
                const float* xr = Xs + (ty * 4 + ri) * 260;
                float a1 = xr[kc + k];
                float a2 = xr[128 + kc + k];
                u64 p1 = packf2(a1, a1);
                u64 p2 = packf2(a2, a2);
#pragma unroll
                for (int j = 0; j < 4; j++) {
                    aN[ri][j] = fma2(p1, wa[j], aN[ri][j]);
                    aN[ri][j] = fma2(p2, wb[j], aN[ri][j]);
                    aA[ri][j] = fma2(p2, wg[j], aA[ri][j]);
                }
            }
        }
    }

    // ---- epilogue: cols for [j] are (tx+32j, tx+32j+16) ----
    float bv[4][2], bgv[4][2];
#pragma unroll
    for (int j = 0; j < 4; j++) {
        bv[j][0]  = bb[tx + 32 * j];       bv[j][1]  = bb[tx + 32 * j + 16];
        bgv[j][0] = bagg[tx + 32 * j];     bgv[j][1] = bagg[tx + 32 * j + 16];
    }

#pragma unroll
    for (int ri = 0; ri < 4; ri++) {
        size_t irow = (size_t)blockIdx.x * 64 + ty * 4 + ri;
        float h[4][2];
#pragma unroll
        for (int j = 0; j < 4; j++) {
            float n0, n1, a0, a1;
            unpackf2(aN[ri][j], n0, n1);
            unpackf2(aA[ri][j], a0, a1);
            float hn0 = n0 + bv[j][0],  hn1 = n1 + bv[j][1];
            float ha0 = a0 + bgv[j][0], ha1 = a1 + bgv[j][1];
            if (!LAST) { hn0 = leakyf(hn0); hn1 = leakyf(hn1);
                         ha0 = leakyf(ha0); ha1 = leakyf(ha1); }
            h[j][0] = hn0 + ha0; h[j][1] = hn1 + ha1;
        }
        if (!LAST) {
            float ss = 0.f;
#pragma unroll
            for (int j = 0; j < 4; j++) ss += h[j][0] * h[j][0] + h[j][1] * h[j][1];
            ss += __shfl_xor_sync(0xffffffffu, ss, 1);
            ss += __shfl_xor_sync(0xffffffffu, ss, 2);
            ss += __shfl_xor_sync(0xffffffffu, ss, 4);
            ss += __shfl_xor_sync(0xffffffffu, ss, 8);
            float inv = 1.0f / fmaxf(sqrtf(ss), 1e-6f);
#pragma unroll
            for (int j = 0; j < 4; j++) { h[j][0] *= inv; h[j][1] *= inv; }
        }
        float* po = out + irow * FEAT;
#pragma unroll
        for (int j = 0; j < 4; j++) {
            po[tx + 32 * j]      = h[j][0];
            po[tx + 32 * j + 16] = h[j][1];
        }
    }
}

// ---------------- launch -----------------------------------------------------
extern "C" void kernel_launch(void* const* d_in, const int* in_sizes, int n_in,
                              void* d_out, int out_size)
{
    const float* node_emb = (const float*)d_in[0];
    const float* content0 = (const float*)d_in[1];
    const float* Wp       = (const float*)d_in[2];
    const float* bp       = (const float*)d_in[3];
    const float* W0       = (const float*)d_in[4];
    const float* b0       = (const float*)d_in[5];
    const float* Wagg0    = (const float*)d_in[6];
    const float* bagg0    = (const float*)d_in[7];
    const float* W1       = (const float*)d_in[8];
    const float* b1       = (const float*)d_in[9];
    const float* Wagg1    = (const float*)d_in[10];
    const float* bagg1    = (const float*)d_in[11];
    const int*   parent0  = (const int*)d_in[12];
    const int*   src0     = (const int*)d_in[13];
    const int*   src1     = (const int*)d_in[15];
    float* out = (float*)d_out;

    (void)in_sizes; (void)n_in; (void)out_size;

    cudaFuncSetAttribute(k_conv<0>, cudaFuncAttributeMaxDynamicSharedMemorySize, CONV_SMEM_BYTES);
    cudaFuncSetAttribute(k_conv<1>, cudaFuncAttributeMaxDynamicSharedMemorySize, CONV_SMEM_BYTES);

    void *p0, *p1;
    cudaGetSymbolAddress(&p0, g_h0);
    cudaGetSymbolAddress(&p1, g_h1);
    float* h0p = (float*)p0;
    float* h1p = (float*)p1;

    k_reset  <<<(S0_N / 16 + 255) / 256, 256>>>();
    k_mark   <<<(9 * S1_N) / 256, 256>>>(src0);
    k_compact<<<S0_N / 256, 256>>>();
    k_h0     <<<S0_N / 128, 256>>>(content0, Wp, bp, node_emb, parent0);
    k_conv<0><<<S1_N / 64, 256, CONV_SMEM_BYTES>>>(h0p, h0p, src0, S1_N,
                                                   W0, b0, Wagg0, bagg0, h1p);
    k_conv<1><<<S2_N / 64, 256, CONV_SMEM_BYTES>>>(h1p, h0p, src1, S2_N,
                                                   W1, b1, Wagg1, bagg1, out);
}